// round 5
// baseline (speedup 1.0000x reference)
#include <cuda_runtime.h>
#include <cuda_bf16.h>

#define FK_EPS 1e-5f
#define J_MAX 128

// Upward ancestor walk with ONE round of affine path-doubling.
// Phase 1: per-joint affine A_j = (R(normalize(w_j)), add_j) in shared.
// Phase 2: C_j = A_{par(j)} o A_j, anc2_j = par^2(j)  (stride-2 chains).
// Phase 3: per-thread walk over the halved chain, no further sync.
__global__ void ForwardKinematicQuat_kernel(
    const float* __restrict__ joint_offsets,   // [J,3]
    const float* __restrict__ root_position,   // [3]
    const float* __restrict__ weight,          // [J,4] (x,y,z,w)
    const int*   __restrict__ parents_raw,     // [J] int32 OR int64 (detected)
    float* __restrict__ out_pos,               // [J,3]
    int J)
{
    __shared__ float4 s_m[J_MAX][3];   // A_j rows: (m0,m1,m2, add_r)
    __shared__ float4 s_c[J_MAX][3];   // C_j rows (doubled affine)
    __shared__ int    s_par[J_MAX];
    __shared__ int    s_anc2[J_MAX];

    const int tid = threadIdx.x;
    const bool live = (tid < J);
    const int j = live ? tid : 0;

    // ---- all independent global loads issued up front (one L2 round) ----
    // int32: word[1] = parents[1] = 0 (forced). int64: word[1] = -1 (sign ext).
    const int  pw1 = __ldg(parents_raw + 1);
    const int  p32 = __ldg(parents_raw + j);
    const int  p64 = __ldg(parents_raw + 2 * j);
    const float4 q = __ldg(reinterpret_cast<const float4*>(weight) + j);
    const float ox = __ldg(joint_offsets + 3 * j + 0);
    const float oy = __ldg(joint_offsets + 3 * j + 1);
    const float oz = __ldg(joint_offsets + 3 * j + 2);
    const float rx = __ldg(root_position + 0);
    const float ry = __ldg(root_position + 1);
    const float rz = __ldg(root_position + 2);

    const bool is64 = (pw1 == -1);
    const int  par  = live ? (is64 ? p64 : p32) : -1;

    if (live) {
        s_par[tid] = par;

        // serial chain: s -> sqrt -> fma -> rcp; quadratics run in parallel
        const float s = q.x * q.x + q.y * q.y + q.z * q.z + q.w * q.w;
        const float n = sqrtf(s);
        const float d = fmaf(2.0f * FK_EPS, n, s) + FK_EPS * FK_EPS;  // (n+eps)^2
        const float inv = __fdividef(1.0f, d);

        const float x2 = q.x * q.x, y2 = q.y * q.y, z2 = q.z * q.z, w2 = q.w * q.w;
        const float xy = q.x * q.y, zw = q.z * q.w, xz = q.x * q.z, yw = q.y * q.w;
        const float yz = q.y * q.z, xw = q.x * q.w;

        const float ax = (par >= 0) ? ox : rx;
        const float ay = (par >= 0) ? oy : ry;
        const float az = (par >= 0) ? oz : rz;

        s_m[tid][0] = make_float4((x2 - y2 - z2 + w2) * inv, 2.f * (xy - zw) * inv,
                                  2.f * (xz + yw) * inv,     ax);
        s_m[tid][1] = make_float4(2.f * (xy + zw) * inv,     (-x2 + y2 - z2 + w2) * inv,
                                  2.f * (yz - xw) * inv,     ay);
        s_m[tid][2] = make_float4(2.f * (xz - yw) * inv,     2.f * (yz + xw) * inv,
                                  (-x2 - y2 + z2 + w2) * inv, az);
    }
    __syncthreads();

    // ---- one path-doubling round: C_j = A_par(j) o A_j, anc2 = par^2 ----
    if (live) {
        if (par >= 0) {
            const float4 a0 = s_m[tid][0];
            const float4 a1 = s_m[tid][1];
            const float4 a2 = s_m[tid][2];
            const float4 p0 = s_m[par][0];
            const float4 p1 = s_m[par][1];
            const float4 p2 = s_m[par][2];
            s_anc2[tid] = s_par[par];
            // Crow_r = p_r.x*a0 + p_r.y*a1 + p_r.z*a2 + (0,0,0,p_r.w)
            float4 c0, c1, c2;
            c0.x = fmaf(p0.x, a0.x, fmaf(p0.y, a1.x, p0.z * a2.x));
            c0.y = fmaf(p0.x, a0.y, fmaf(p0.y, a1.y, p0.z * a2.y));
            c0.z = fmaf(p0.x, a0.z, fmaf(p0.y, a1.z, p0.z * a2.z));
            c0.w = fmaf(p0.x, a0.w, fmaf(p0.y, a1.w, fmaf(p0.z, a2.w, p0.w)));
            c1.x = fmaf(p1.x, a0.x, fmaf(p1.y, a1.x, p1.z * a2.x));
            c1.y = fmaf(p1.x, a0.y, fmaf(p1.y, a1.y, p1.z * a2.y));
            c1.z = fmaf(p1.x, a0.z, fmaf(p1.y, a1.z, p1.z * a2.z));
            c1.w = fmaf(p1.x, a0.w, fmaf(p1.y, a1.w, fmaf(p1.z, a2.w, p1.w)));
            c2.x = fmaf(p2.x, a0.x, fmaf(p2.y, a1.x, p2.z * a2.x));
            c2.y = fmaf(p2.x, a0.y, fmaf(p2.y, a1.y, p2.z * a2.y));
            c2.z = fmaf(p2.x, a0.z, fmaf(p2.y, a1.z, p2.z * a2.z));
            c2.w = fmaf(p2.x, a0.w, fmaf(p2.y, a1.w, fmaf(p2.z, a2.w, p2.w)));
            s_c[tid][0] = c0;
            s_c[tid][1] = c1;
            s_c[tid][2] = c2;
        } else {
            s_anc2[tid] = -1;
            s_c[tid][0] = s_m[tid][0];
            s_c[tid][1] = s_m[tid][1];
            s_c[tid][2] = s_m[tid][2];
        }
    }
    __syncthreads();

    if (!live) return;

    // ---- walk the halved chain ----
    float vx = ox, vy = oy, vz = oz;
    int a = par;
    while (a >= 0) {
        const float4 r0 = s_c[a][0];
        const float4 r1 = s_c[a][1];
        const float4 r2 = s_c[a][2];
        const int an = s_anc2[a];         // serial LDS chase paces the loop
        float nx = fmaf(r0.x, vx, fmaf(r0.y, vy, fmaf(r0.z, vz, r0.w)));
        float ny = fmaf(r1.x, vx, fmaf(r1.y, vy, fmaf(r1.z, vz, r1.w)));
        float nz = fmaf(r2.x, vx, fmaf(r2.y, vy, fmaf(r2.z, vz, r2.w)));
        vx = nx; vy = ny; vz = nz;
        a = an;
    }

    if (par < 0) { vx = rx; vy = ry; vz = rz; }

    out_pos[3 * tid + 0] = vx;
    out_pos[3 * tid + 1] = vy;
    out_pos[3 * tid + 2] = vz;
}

extern "C" void kernel_launch(void* const* d_in, const int* in_sizes, int n_in,
                              void* d_out, int out_size) {
    const float* joint_offsets = (const float*)d_in[0];
    const float* root_position = (const float*)d_in[1];
    const float* weight        = (const float*)d_in[2];
    const int*   parents       = (const int*)d_in[3];

    const int J = in_sizes[2] / 4;          // weight is [J,4]
    int threads = ((J + 31) / 32) * 32;
    if (threads < 64) threads = 64;
    if (threads > J_MAX) threads = J_MAX;

    ForwardKinematicQuat_kernel<<<1, threads>>>(
        joint_offsets, root_position, weight, parents, (float*)d_out, J);
}